// round 13
// baseline (speedup 1.0000x reference)
#include <cuda_runtime.h>
#include <cuda_fp16.h>
#include <cstdint>

#define BATCH 4
#define C 192
#define HW 256
#define HO 128
#define NPIX (HO*HO)      // 16384
#define NPIXF (HW*HW)     // 65536
#define HEADS 8
#define CQH 24
#define CAH 12
#define CA 96
#define KKDIM (C*9)       // 1728
#define PLANE (129*132)
#define NSPLIT 32
#define DOTP 640
#define KC_AS 6400
#define KC_BS 4352

// ---------------- scratch ----------------
__device__ float    g_q[BATCH*C*NPIX];
__device__ float    g_k[BATCH*C*NPIX];
__device__ float    g_adw[BATCH*C*NPIX];
__device__ float    g_a[BATCH*CA*NPIX];
__device__ __align__(16) __half g_vh[(size_t)BATCH*C*NPIXF];  // v as fp16
__device__ unsigned g_xp[(size_t)BATCH*C*4*PLANE];   // tf32 bits
__device__ unsigned g_wkT[KKDIM*C];                  // tf32 bits
__device__ unsigned g_wvT[C*C];                      // tf32 bits
__device__ unsigned g_weffT[BATCH*C*C];              // tf32 bits
__device__ float    g_dotp[(size_t)NSPLIT*BATCH*HEADS*DOTP];

// ---------------- helpers ----------------
__device__ __forceinline__ unsigned f2tf(float f){
    unsigned r; asm("cvt.rna.tf32.f32 %0, %1;" : "=r"(r) : "f"(f)); return r;
}
__device__ __forceinline__ void mma_tf32(float& c0, float& c1, float& c2, float& c3,
                                         unsigned a0, unsigned a1, unsigned a2, unsigned a3,
                                         unsigned b0, unsigned b1){
    asm volatile("mma.sync.aligned.m16n8k8.row.col.f32.tf32.tf32.f32 "
                 "{%0,%1,%2,%3},{%4,%5,%6,%7},{%8,%9},{%0,%1,%2,%3};"
                 : "+f"(c0), "+f"(c1), "+f"(c2), "+f"(c3)
                 : "r"(a0), "r"(a1), "r"(a2), "r"(a3), "r"(b0), "r"(b1));
}
__device__ __forceinline__ void cpa16(void* s, const void* g){
    unsigned sa = (unsigned)__cvta_generic_to_shared(s);
    asm volatile("cp.async.ca.shared.global [%0],[%1],16;" :: "r"(sa), "l"(g));
}
__device__ __forceinline__ void cpa4(void* s, const void* g){
    unsigned sa = (unsigned)__cvta_generic_to_shared(s);
    asm volatile("cp.async.ca.shared.global [%0],[%1],4;" :: "r"(sa), "l"(g));
}
#define CP_COMMIT asm volatile("cp.async.commit_group;")

// ================= zp + prep kernel (launch 0) ==============================
#define PREP_N 1440
#define ZP_N   (BATCH*C*4)
__global__ __launch_bounds__(256) void zp_prep_kernel(const float* __restrict__ wk,
                                                      const float* __restrict__ wv)
{
    int bid = blockIdx.x;
    if (bid < ZP_N) {
        size_t base = (size_t)bid * PLANE;
        for (int i = threadIdx.x; i < 260; i += 256) {
            if (i < 132) g_xp[base + i] = 0u;
            else         g_xp[base + (i - 131)*132] = 0u;
        }
    } else {
        int i = (bid - ZP_N) * 256 + threadIdx.x;
        if (i < KKDIM*C) {
            int k = i / C, oc = i % C;
            g_wkT[i] = f2tf(wk[oc*KKDIM + k]);
        } else {
            int j = i - KKDIM*C;
            if (j < C*C) {
                int ic = j / C, oc = j % C;
                g_wvT[j] = f2tf(wv[oc*C + ic]);
            }
        }
    }
}

// ================= sdq kernel (launches 1 and 2, halves) ====================
// xs layout: cols 0..63 hold logical cc = 1..64 (16B-aligned loads),
//            col 64 holds logical cc = 0.
#define SDQ_N (16*BATCH*C)
__global__ __launch_bounds__(256) void sdq_kernel(int base,
                                                  const float* __restrict__ x,
                                                  const float* __restrict__ wq,
                                                  const float* __restrict__ wadw)
{
    __shared__ float xs[66][68];
    int bid = base + blockIdx.x;
    int tile = bid & 15;
    int bc   = bid >> 4;
    int c    = bc % C;
    int oy0 = (tile >> 2) * 32, ox0 = (tile & 3) * 32;
    int iy0 = 2*oy0 - 1, ix0 = 2*ox0 - 1;
    int ixA = ix0 + 1;
    const float* xp = x + (size_t)bc * NPIXF;
    int tid = threadIdx.x;

    for (int i = tid; i < 66*16; i += 256) {
        int r = i >> 4, seg = i & 15;
        int iy = iy0 + r;
        float4 v = make_float4(0.f, 0.f, 0.f, 0.f);
        if (iy >= 0 && iy < HW) v = *(const float4*)&xp[iy*HW + ixA + seg*4];
        *(float4*)&xs[r][seg*4] = v;
    }
    if (tid < 66) {
        int iy = iy0 + tid;
        float v = 0.f;
        if (iy >= 0 && iy < HW && ix0 >= 0) v = xp[iy*HW + ix0];
        xs[tid][64] = v;
    }
    __syncthreads();

    size_t pbase = (size_t)bc * 4 * PLANE;
    for (int i = tid; i < 4096; i += 256) {
        int ly = i >> 6, lx = i & 63;
        int ph = ((ly & 1) << 1) | (lx & 1);
        g_xp[pbase + (size_t)ph*PLANE + (oy0 + (ly>>1) + 1)*132 + ox0 + (lx>>1) + 1]
            = f2tf(xs[ly + 1][lx]);
    }

    float wqr[9], war[9];
#pragma unroll
    for (int i = 0; i < 9; i++) { wqr[i] = wq[c*9+i]; war[i] = wadw[c*9+i]; }
#pragma unroll
    for (int j = 0; j < 4; j++) {
        int oyl = (tid >> 5) + j*8, oxl = tid & 31;
        float aq = 0.f, aa = 0.f;
#pragma unroll
        for (int ky = 0; ky < 3; ky++)
#pragma unroll
            for (int kx = 0; kx < 3; kx++) {
                int cl = 2*oxl + kx;
                float v = (cl == 0) ? xs[2*oyl + ky][64] : xs[2*oyl + ky][cl - 1];
                aq = fmaf(wqr[ky*3+kx], v, aq);
                aa = fmaf(war[ky*3+kx], v, aa);
            }
        size_t o = (size_t)bc * NPIX + (oy0 + oyl)*HO + ox0 + oxl;
        g_q[o] = aq;
        g_adw[o] = aa;
    }
}

// ================= kconv body: pipelined tf32 implicit GEMM =================
__device__ __forceinline__ void kconv_fillB(unsigned* dstBase, const int* rowoff,
                                            int k0, int tid)
{
    for (int i = tid; i < 1024; i += 256) {
        int kk = i >> 5, g4 = i & 31;
        int pr = g4 >> 2, pc = (g4 & 3) * 4;
        int ro = rowoff[k0 + kk];
        const unsigned* gp = &g_xp[ro + pr*132 + pc];
        unsigned* sp = &dstBase[kk*136 + pr*16 + pc];
        if ((ro & 3) == 0) {
            cpa16(sp, gp);
        } else {
            cpa4(sp,     gp);
            cpa4(sp + 1, gp + 1);
            cpa4(sp + 2, gp + 2);
            cpa4(sp + 3, gp + 3);
        }
    }
}

__device__ void kconv_body(int bid)
{
    extern __shared__ unsigned smm[];
    unsigned* Asm = smm;
    unsigned* Bsm = smm + 2*KC_AS;
    int* rowoff = (int*)(smm + 2*KC_AS + 2*KC_BS);

    int b = bid >> 7;
    int tile = bid & 127;
    int oy0 = (tile >> 3) * 8, ox0 = (tile & 7) * 16;
    int tid = threadIdx.x;
    int warp = tid >> 5, lane = tid & 31;
    int wm = warp >> 1, wn = warp & 1;
    int g = lane >> 2, tg = lane & 3;

    for (int k = tid; k < KKDIM; k += 256) {
        int ic = k / 9, t = k - ic*9;
        int ky = t / 3, kx = t - ky*3;
        int py = (ky == 1) ? 0 : 1, px = (kx == 1) ? 0 : 1;
        int dy = (ky == 0) ? 0 : 1, dx = (kx == 0) ? 0 : 1;
        rowoff[k] = ((b*C + ic)*4 + py*2 + px)*PLANE + (oy0+dy)*132 + (ox0+dx);
    }
    __syncthreads();

    float acc[3][8][4];
#pragma unroll
    for (int mf = 0; mf < 3; mf++)
#pragma unroll
        for (int nf = 0; nf < 8; nf++)
#pragma unroll
            for (int q = 0; q < 4; q++) acc[mf][nf][q] = 0.f;

    for (int i = tid; i < 1536; i += 256) {
        int kk = i / 48, m4 = (i % 48) * 4;
        cpa16(&Asm[kk*200 + m4], &g_wkT[kk*C + m4]);
    }
    kconv_fillB(Bsm, rowoff, 0, tid);
    CP_COMMIT;

#pragma unroll 1
    for (int c2 = 0; c2 < 54; c2++) {
        int p = c2 & 1;
        if (c2 + 1 < 54) {
            int q2 = p ^ 1;
            int k0 = (c2 + 1) * 32;
            for (int i = tid; i < 1536; i += 256) {
                int kk = i / 48, m4 = (i % 48) * 4;
                cpa16(&Asm[q2*KC_AS + kk*200 + m4], &g_wkT[(k0+kk)*C + m4]);
            }
            kconv_fillB(&Bsm[q2*KC_BS], rowoff, k0, tid);
            CP_COMMIT;
            asm volatile("cp.async.wait_group 1;");
        } else {
            asm volatile("cp.async.wait_group 0;");
        }
        __syncthreads();

        const unsigned* Ab = &Asm[p*KC_AS];
        const unsigned* Bb = &Bsm[p*KC_BS];
#pragma unroll
        for (int k8 = 0; k8 < 4; k8++) {
            int kb = k8 * 8;
            unsigned a[3][4], bb[8][2];
#pragma unroll
            for (int mf = 0; mf < 3; mf++) {
                int mb = wm*48 + mf*16 + g;
                a[mf][0] = Ab[(kb+tg)*200 + mb];     a[mf][1] = Ab[(kb+tg)*200 + mb + 8];
                a[mf][2] = Ab[(kb+tg+4)*200 + mb];   a[mf][3] = Ab[(kb+tg+4)*200 + mb + 8];
            }
#pragma unroll
            for (int nf = 0; nf < 8; nf++) {
                int nb = wn*64 + nf*8 + g;
                bb[nf][0] = Bb[(kb+tg)*136 + nb];    bb[nf][1] = Bb[(kb+tg+4)*136 + nb];
            }
#pragma unroll
            for (int mf = 0; mf < 3; mf++)
#pragma unroll
                for (int nf = 0; nf < 8; nf++)
                    mma_tf32(acc[mf][nf][0], acc[mf][nf][1], acc[mf][nf][2], acc[mf][nf][3],
                             a[mf][0], a[mf][1], a[mf][2], a[mf][3], bb[nf][0], bb[nf][1]);
        }
        __syncthreads();
    }

#pragma unroll
    for (int mf = 0; mf < 3; mf++)
#pragma unroll
        for (int nf = 0; nf < 8; nf++) {
            int m = wm*48 + mf*16 + g;
            int n = wn*64 + nf*8 + tg*2;
            int oy = oy0 + (n >> 4), ox = ox0 + (n & 15);
            *(float2*)&g_k[(size_t)(b*C + m)*NPIX + oy*HO + ox] =
                make_float2(acc[mf][nf][0], acc[mf][nf][1]);
            *(float2*)&g_k[(size_t)(b*C + m + 8)*NPIX + oy*HO + ox] =
                make_float2(acc[mf][nf][2], acc[mf][nf][3]);
        }
}

// ================= tgemm body: M=192 x N=128, K=192 =========================
// MODE 0: B = x (fp32, staged LDG->tf32); out -> g_vh (half) with illu
// MODE 1: B = g_vh (half, staged LDG->tf32); out -> fp32 buffer
template<int MODE>
__device__ void tgemm_body(int bid, const float* __restrict__ xin,
                           const float* __restrict__ illu,
                           float* __restrict__ outp)
{
    extern __shared__ unsigned smm[];
    unsigned* Asm = smm;
    unsigned* Bsm = smm + 2*KC_AS;

    int b = bid >> 9;
    int n0 = (bid & 511) * 128;
    const unsigned* A = (MODE == 0) ? g_wvT : (g_weffT + (size_t)b*C*C);
    const float* Bf = (MODE == 0) ? (xin + (size_t)b*C*NPIXF) : nullptr;
    const __half* Bu = (MODE == 1) ? (g_vh + (size_t)b*C*NPIXF) : nullptr;
    const float* Ib = (MODE == 0) ? (illu + (size_t)b*C*NPIXF) : nullptr;

    int tid = threadIdx.x;
    int warp = tid >> 5, lane = tid & 31;
    int wm = warp >> 1, wn = warp & 1;
    int g = lane >> 2, tg = lane & 3;

    float acc[3][8][4];
#pragma unroll
    for (int mf = 0; mf < 3; mf++)
#pragma unroll
        for (int nf = 0; nf < 8; nf++)
#pragma unroll
            for (int q = 0; q < 4; q++) acc[mf][nf][q] = 0.f;

    for (int i = tid; i < 1536; i += 256) {
        int kk = i / 48, m4 = (i % 48) * 4;
        cpa16(&Asm[kk*200 + m4], &A[kk*C + m4]);
    }
    CP_COMMIT;
#pragma unroll
    for (int j = 0; j < 4; j++) {
        int i = tid + j*256;
        int kk = i >> 5, n4 = (i & 31) * 4;
        uint4 u;
        if (MODE == 0) {
            float4 t = *(const float4*)&Bf[(size_t)kk*NPIXF + n0 + n4];
            u = make_uint4(f2tf(t.x), f2tf(t.y), f2tf(t.z), f2tf(t.w));
        } else {
            uint2 hraw = *(const uint2*)&Bu[(size_t)kk*NPIXF + n0 + n4];
            float2 f0 = __half22float2(*(__half2*)&hraw.x);
            float2 f1 = __half22float2(*(__half2*)&hraw.y);
            u = make_uint4(f2tf(f0.x), f2tf(f0.y), f2tf(f1.x), f2tf(f1.y));
        }
        *(uint4*)&Bsm[kk*136 + n4] = u;
    }

    float4 tmpf[4];
    uint2  tmph[4];
#pragma unroll 1
    for (int c2 = 0; c2 < 6; c2++) {
        int p = c2 & 1;
        int q2 = p ^ 1;
        if (c2 + 1 < 6) {
            int k0 = (c2 + 1) * 32;
            for (int i = tid; i < 1536; i += 256) {
                int kk = i / 48, m4 = (i % 48) * 4;
                cpa16(&Asm[q2*KC_AS + kk*200 + m4], &A[(k0+kk)*C + m4]);
            }
            CP_COMMIT;
#pragma unroll
            for (int j = 0; j < 4; j++) {
                int i = tid + j*256;
                int kk = i >> 5, n4 = (i & 31) * 4;
                if (MODE == 0)
                    tmpf[j] = *(const float4*)&Bf[(size_t)(k0+kk)*NPIXF + n0 + n4];
                else
                    tmph[j] = *(const uint2*)&Bu[(size_t)(k0+kk)*NPIXF + n0 + n4];
            }
            asm volatile("cp.async.wait_group 1;");
        } else {
            asm volatile("cp.async.wait_group 0;");
        }
        __syncthreads();

        const unsigned* Ab = &Asm[p*KC_AS];
        const unsigned* Bb = &Bsm[p*KC_BS];
#pragma unroll
        for (int k8 = 0; k8 < 4; k8++) {
            int kb = k8 * 8;
            unsigned a[3][4], bb[8][2];
#pragma unroll
            for (int mf = 0; mf < 3; mf++) {
                int mb = wm*48 + mf*16 + g;
                a[mf][0] = Ab[(kb+tg)*200 + mb];     a[mf][1] = Ab[(kb+tg)*200 + mb + 8];
                a[mf][2] = Ab[(kb+tg+4)*200 + mb];   a[mf][3] = Ab[(kb+tg+4)*200 + mb + 8];
            }
#pragma unroll
            for (int nf = 0; nf < 8; nf++) {
                int nb = wn*64 + nf*8 + g;
                bb[nf][0] = Bb[(kb+tg)*136 + nb];    bb[nf][1] = Bb[(kb+tg+4)*136 + nb];
            }
#pragma unroll
            for (int mf = 0; mf < 3; mf++)
#pragma unroll
                for (int nf = 0; nf < 8; nf++)
                    mma_tf32(acc[mf][nf][0], acc[mf][nf][1], acc[mf][nf][2], acc[mf][nf][3],
                             a[mf][0], a[mf][1], a[mf][2], a[mf][3], bb[nf][0], bb[nf][1]);
        }
        if (c2 + 1 < 6) {
#pragma unroll
            for (int j = 0; j < 4; j++) {
                int i = tid + j*256;
                int kk = i >> 5, n4 = (i & 31) * 4;
                uint4 u;
                if (MODE == 0) {
                    u = make_uint4(f2tf(tmpf[j].x), f2tf(tmpf[j].y),
                                   f2tf(tmpf[j].z), f2tf(tmpf[j].w));
                } else {
                    float2 f0 = __half22float2(*(__half2*)&tmph[j].x);
                    float2 f1 = __half22float2(*(__half2*)&tmph[j].y);
                    u = make_uint4(f2tf(f0.x), f2tf(f0.y), f2tf(f1.x), f2tf(f1.y));
                }
                *(uint4*)&Bsm[q2*KC_BS + kk*136 + n4] = u;
            }
        }
        __syncthreads();
    }

#pragma unroll
    for (int mf = 0; mf < 3; mf++)
#pragma unroll
        for (int nf = 0; nf < 8; nf++) {
            int m = wm*48 + mf*16 + g;
            int n = n0 + wn*64 + nf*8 + tg*2;
            if (MODE == 0) {
                float2 i0 = *(const float2*)&Ib[(size_t)m*NPIXF + n];
                float2 i1 = *(const float2*)&Ib[(size_t)(m+8)*NPIXF + n];
                __half* O = g_vh + (size_t)b*C*NPIXF;
                *(__half2*)&O[(size_t)m*NPIXF + n] =
                    __floats2half2_rn(acc[mf][nf][0]*i0.x, acc[mf][nf][1]*i0.y);
                *(__half2*)&O[(size_t)(m+8)*NPIXF + n] =
                    __floats2half2_rn(acc[mf][nf][2]*i1.x, acc[mf][nf][3]*i1.y);
            } else {
                float* O = outp + (size_t)b*C*NPIXF;
                *(float2*)&O[(size_t)m*NPIXF + n] =
                    make_float2(acc[mf][nf][0], acc[mf][nf][1]);
                *(float2*)&O[(size_t)(m+8)*NPIXF + n] =
                    make_float2(acc[mf][nf][2], acc[mf][nf][3]);
            }
        }
}

// ================= apw body: pointwise 192->96 (+bias) ======================
__device__ void apw_body(int bid, const float* __restrict__ wapw,
                         const float* __restrict__ bapw)
{
    extern __shared__ unsigned smm[];
    float* s = (float*)smm;               // C*64 floats = 48KB
    int b = bid >> 8;
    int p0 = (bid & 255) * 64;
    for (int i = threadIdx.x; i < C*64; i += 256) {
        int cc = i >> 6, pp = i & 63;
        s[i] = g_adw[(size_t)(b*C + cc)*NPIX + p0 + pp];
    }
    __syncthreads();
    int pg  = threadIdx.x & 15;
    int ocb = threadIdx.x >> 4;
    for (int oc = ocb; oc < CA; oc += 16) {
        float bsv = bapw[oc];
        float4 acc = make_float4(bsv, bsv, bsv, bsv);
        for (int ic = 0; ic < C; ic++) {
            float w = __ldg(&wapw[oc*C + ic]);
            float4 xv = *reinterpret_cast<const float4*>(&s[ic*64 + pg*4]);
            acc.x = fmaf(w, xv.x, acc.x);
            acc.y = fmaf(w, xv.y, acc.y);
            acc.z = fmaf(w, xv.z, acc.z);
            acc.w = fmaf(w, xv.w, acc.w);
        }
        *reinterpret_cast<float4*>(&g_a[(size_t)(b*CA + oc)*NPIX + p0 + pg*4]) = acc;
    }
}

// ================= fat kernel: kconv + tgemm0 + apw (launch index 3) ========
#define KCONV_N 512
#define TG0_N   2048
#define APW_N   1024
__global__ __launch_bounds__(256) void fat_kernel(const float* __restrict__ x,
                                                  const float* __restrict__ illu,
                                                  const float* __restrict__ wapw,
                                                  const float* __restrict__ bapw)
{
    int bid = blockIdx.x;
    if (bid < KCONV_N)            kconv_body(bid);
    else if (bid < KCONV_N+TG0_N) tgemm_body<0>(bid - KCONV_N, x, illu, nullptr);
    else                          apw_body(bid - KCONV_N - TG0_N, wapw, bapw);
}

__global__ __launch_bounds__(256) void tgemm1_kernel(float* __restrict__ outp)
{
    tgemm_body<1>(blockIdx.x, nullptr, nullptr, outp);
}

// ================= attention dots + fused norms =============================
__global__ __launch_bounds__(768) void attn_kernel()
{
    __shared__ float a_s[CAH][256];
    int split = blockIdx.x, bh = blockIdx.y;
    int b = bh >> 3, h = bh & 7;
    int tid = threadIdx.x, warp = tid >> 5, lane = tid & 31;
    const float* qp = g_q + (size_t)(b*C + h*CQH + warp)*NPIX;
    const float* kp = g_k + (size_t)(b*C + h*CQH + warp)*NPIX;
    const float* ap = g_a + (size_t)(b*CA + h*CAH)*NPIX;
    int p0 = split * (NPIX / NSPLIT);

    float dq[12], dk[12];
#pragma unroll
    for (int d = 0; d < 12; d++) { dq[d] = 0.f; dk[d] = 0.f; }
    float qq = 0.f, kk = 0.f, aa = 0.f;

    for (int c0 = 0; c0 < NPIX/NSPLIT; c0 += 256) {
        for (int i = tid; i < CAH*256; i += 768) {
            int d = i >> 8, p = i & 255;
            a_s[d][p] = ap[(size_t)d*NPIX + p0 + c0 + p];
        }
        __syncthreads();
#pragma unroll
        for (int hf = 0; hf < 2; hf++) {
            int p = hf*128 + lane*4;
            float4 qv = *(const float4*)&qp[p0 + c0 + p];
            float4 kv = *(const float4*)&kp[p0 + c0 + p];
            qq += qv.x*qv.x + qv.y*qv.y + qv.z*qv.z + qv.w*qv.w;
            kk += kv.x*kv.x + kv.y*kv.y + kv.z*kv.z + kv.w*kv.w;
            if (warp < CAH) {
                float4 av = *(const float4*)&a_s[warp][p];
                aa += av.x*av.x + av.y*av.y + av.z*av.z + av.w*av.w;
            }
#pragma unroll
            for (int d = 0; d < 12; d++) {
                float4 av = *(const float4*)&a_s[d][p];
                dq[d] += qv.x*av.x + qv.y*av.y + qv.z*av.z + qv.w*av.w;
                dk[d] += kv.x*av.x + kv.y*av.y + kv.z*av.z + kv.w*av.w;
            }
        }
        __syncthreads();
    }
#pragma unroll
    for (int off = 16; off; off >>= 1) {
#pragma unroll
        for (int d = 0; d < 12; d++) {
            dq[d] += __shfl_down_sync(0xffffffffu, dq[d], off);
            dk[d] += __shfl_down_sync(0xffffffffu, dk[d], off);
        }
        qq += __shfl_down_sync(0xffffffffu, qq, off);
        kk += __shfl_down_sync(0xffffffffu, kk, off);
        aa += __shfl_down_sync(0xffffffffu, aa, off);
    }
    if (lane == 0) {
        float* out = &g_dotp[((size_t)split*BATCH*HEADS + bh)*DOTP];
#pragma unroll
        for (int d = 0; d < 12; d++) {
            out[warp*12 + d]       = dq[d];
            out[288 + warp*12 + d] = dk[d];
        }
        out[576 + warp] = qq;
        out[600 + warp] = kk;
        if (warp < 12) out[624 + warp] = aa;
    }
}

// ================= combine: norms, softmax, M, W_eff^T slice (tf32) =========
#define WSLICE (C*C/64)      // 576
__global__ __launch_bounds__(256) void combine_kernel(const float* __restrict__ wo,
                                                      const float* __restrict__ ta,
                                                      const float* __restrict__ tv)
{
    __shared__ float buf[HEADS*DOTP];
    __shared__ float SA[HEADS][CQH][CAH];
    __shared__ float SK[HEADS][CAH][CQH];
    int slice = blockIdx.x, b = blockIdx.y, tid = threadIdx.x;

    for (int i = tid; i < HEADS*DOTP; i += 256) {
        int h = i / DOTP, e = i - h*DOTP;
        float s = 0.f;
#pragma unroll
        for (int sp = 0; sp < NSPLIT; sp++)
            s += g_dotp[((size_t)sp*BATCH*HEADS + b*HEADS + h)*DOTP + e];
        buf[i] = s;
    }
    __syncthreads();

    if (tid < HEADS*CQH) {
        int h = tid / CQH, c = tid % CQH;
        const float* B = &buf[h*DOTP];
        float invq = 1.f / fmaxf(sqrtf(B[576 + c]), 1e-12f);
        float tah = ta[h];
        float l[CAH], m = -1e30f;
#pragma unroll
        for (int d = 0; d < CAH; d++) {
            float inva = 1.f / fmaxf(sqrtf(B[624 + d]), 1e-12f);
            l[d] = B[c*12 + d] * invq * inva * tah;
            m = fmaxf(m, l[d]);
        }
        float s = 0.f;
#pragma unroll
        for (int d = 0; d < CAH; d++) { l[d] = expf(l[d] - m); s += l[d]; }
        float inv = 1.f / s;
#pragma unroll
        for (int d = 0; d < CAH; d++) SA[h][c][d] = l[d] * inv;
    }
    if (tid < HEADS*CAH) {
        int h = tid / CAH, d = tid % CAH;
        const float* B = &buf[h*DOTP];
        float inva = 1.f / fmaxf(sqrtf(B[624 + d]), 1e-12f);
        float tvh = tv[h];
        float l[CQH], m = -1e30f;
#pragma unroll
        for (int c = 0; c < CQH; c++) {
            float invk = 1.f / fmaxf(sqrtf(B[600 + c]), 1e-12f);
            l[c] = B[288 + c*12 + d] * invk * inva * tvh;
            m = fmaxf(m, l[c]);
        }
        float s = 0.f;
#pragma unroll
        for (int c = 0; c < CQH; c++) { l[c] = expf(l[c] - m); s += l[c]; }
        float inv = 1.f / s;
#pragma unroll
        for (int c = 0; c < CQH; c++) SK[h][d][c] = l[c] * inv;
    }
    __syncthreads();

    float* M = buf;
    for (int i = tid; i < HEADS*CQH*CQH; i += 256) {
        int h = i / (CQH*CQH), r = (i / CQH) % CQH, j = i % CQH;
        float s = 0.f;
#pragma unroll
        for (int d = 0; d < CAH; d++) s = fmaf(SA[h][r][d], SK[h][d][j], s);
        M[(h*CQH + r)*CQH + j] = s;
    }
    __syncthreads();

    int base = slice * WSLICE;
    for (int i = base + tid; i < base + WSLICE; i += 256) {
        int cv = i / C, o = i % C;
        int hv = cv / CQH, j = cv % CQH;
        float s = 0.f;
#pragma unroll
        for (int k = 0; k < CQH; k++)
            s = fmaf(wo[o*C + hv*CQH + k], M[(hv*CQH + k)*CQH + j], s);
        g_weffT[(size_t)b*C*C + i] = f2tf(s);
    }
}

// ================= launch ===================================================
extern "C" void kernel_launch(void* const* d_in, const int* in_sizes, int n_in,
                              void* d_out, int out_size)
{
    const float* x    = (const float*)d_in[0];
    const float* illu = (const float*)d_in[1];
    const float* wq   = (const float*)d_in[2];
    const float* wk   = (const float*)d_in[3];
    const float* wadw = (const float*)d_in[4];
    const float* wapw = (const float*)d_in[5];
    const float* bapw = (const float*)d_in[6];
    const float* wv   = (const float*)d_in[7];
    const float* wo   = (const float*)d_in[8];
    const float* ta   = (const float*)d_in[9];
    const float* tv   = (const float*)d_in[10];
    float* out = (float*)d_out;

    const int fat_smem = (2*KC_AS + 2*KC_BS + KKDIM) * 4;   // 92928
    const int tg_smem  = (2*KC_AS + 2*KC_BS) * 4;           // 86016
    cudaFuncSetAttribute(fat_kernel, cudaFuncAttributeMaxDynamicSharedMemorySize, fat_smem);
    cudaFuncSetAttribute(tgemm1_kernel, cudaFuncAttributeMaxDynamicSharedMemorySize, tg_smem);

    // launch indices 0..2 (preproc pieces), 3 = fat (ncu captures index 3)
    zp_prep_kernel<<<ZP_N + PREP_N, 256>>>(wk, wv);
    sdq_kernel    <<<SDQ_N/2, 256>>>(0,        x, wq, wadw);
    sdq_kernel    <<<SDQ_N/2, 256>>>(SDQ_N/2,  x, wq, wadw);
    fat_kernel    <<<KCONV_N + TG0_N + APW_N, 256, fat_smem>>>(x, illu, wapw, bapw);
    attn_kernel   <<<dim3(NSPLIT, BATCH*HEADS), 768>>>();
    combine_kernel<<<dim3(64, BATCH), 256>>>(wo, ta, tv);
    tgemm1_kernel <<<TG0_N, 256, tg_smem>>>(out);
}

// round 14
// speedup vs baseline: 1.1640x; 1.1640x over previous
#include <cuda_runtime.h>
#include <cuda_fp16.h>
#include <cstdint>

#define BATCH 4
#define C 192
#define HW 256
#define HO 128
#define NPIX (HO*HO)      // 16384
#define NPIXF (HW*HW)     // 65536
#define HEADS 8
#define CQH 24
#define CAH 12
#define CA 96
#define KKDIM (C*9)       // 1728
#define PLANE (129*132)
#define NSPLIT 16
#define DOTP 640
#define APITCH 200        // halves
#define BPITCH 136        // halves
#define ABUF (32*APITCH)  // 6400 halves
#define BBUF (32*BPITCH)  // 4352 halves

// ---------------- scratch ----------------
__device__ float    g_q[BATCH*C*NPIX];
__device__ float    g_k[BATCH*C*NPIX];
__device__ float    g_adw[BATCH*C*NPIX];
__device__ float    g_a[BATCH*CA*NPIX];
__device__ __align__(16) __half g_vh[(size_t)BATCH*C*NPIXF];
__device__ unsigned g_xp[(size_t)BATCH*C*4*PLANE];            // tf32/f32 bits
__device__ __align__(16) __half g_wkTh[KKDIM*C];              // [k][oc]
__device__ __align__(16) __half g_wvTh[C*C];                  // [ic][oc]
__device__ __align__(16) __half g_weffTh[BATCH*C*C];          // [cv][o]
__device__ float    g_dotp[(size_t)NSPLIT*BATCH*HEADS*DOTP];

// ---------------- helpers ----------------
__device__ __forceinline__ unsigned f2tf(float f){
    unsigned r; asm("cvt.rna.tf32.f32 %0, %1;" : "=r"(r) : "f"(f)); return r;
}
__device__ __forceinline__ unsigned s2u(const void* p){
    return (unsigned)__cvta_generic_to_shared(p);
}
__device__ __forceinline__ void ldsm4t(unsigned* r, unsigned addr){
    asm volatile("ldmatrix.sync.aligned.m8n8.x4.trans.shared.b16 {%0,%1,%2,%3}, [%4];"
                 : "=r"(r[0]),"=r"(r[1]),"=r"(r[2]),"=r"(r[3]) : "r"(addr));
}
__device__ __forceinline__ void mma_f16(float* c, const unsigned* a, unsigned b0, unsigned b1){
    asm volatile("mma.sync.aligned.m16n8k16.row.col.f32.f16.f16.f32 "
                 "{%0,%1,%2,%3},{%4,%5,%6,%7},{%8,%9},{%0,%1,%2,%3};"
                 : "+f"(c[0]),"+f"(c[1]),"+f"(c[2]),"+f"(c[3])
                 : "r"(a[0]),"r"(a[1]),"r"(a[2]),"r"(a[3]),"r"(b0),"r"(b1));
}
__device__ __forceinline__ void cpa16(void* s, const void* g){
    unsigned sa = (unsigned)__cvta_generic_to_shared(s);
    asm volatile("cp.async.ca.shared.global [%0],[%1],16;" :: "r"(sa), "l"(g));
}
#define CP_COMMIT asm volatile("cp.async.commit_group;")

// fp16 MMA consumer: A_s[k][m] pitch APITCH, B_s[k][n] pitch BPITCH, K-chunk 32
// warp tile 48M x 64N (wm in 0..3, wn in 0..1). Validated in R11.
__device__ __forceinline__ void mma_chunk(const __half* Ab, const __half* Bb,
                                          float acc[3][8][4], int wm, int wn, int lane)
{
    int aRow = (lane & 7) + ((lane & 16) ? 8 : 0);
    int aCol = wm*48 + ((lane & 8) ? 8 : 0);
    int bRow = (lane & 7) + ((lane & 8) ? 8 : 0);
    int bCol = wn*64 + ((lane & 16) ? 8 : 0);
    unsigned aBase = s2u(Ab), bBase = s2u(Bb);
#pragma unroll
    for (int ks = 0; ks < 2; ks++) {
        int kb = ks*16;
        unsigned a[3][4];
#pragma unroll
        for (int mf = 0; mf < 3; mf++)
            ldsm4t(a[mf], aBase + (unsigned)(((kb + aRow)*APITCH + aCol + mf*16)*2));
        unsigned bb[8][2];
#pragma unroll
        for (int j = 0; j < 4; j++) {
            unsigned r[4];
            ldsm4t(r, bBase + (unsigned)(((kb + bRow)*BPITCH + bCol + j*16)*2));
            bb[2*j][0] = r[0]; bb[2*j][1] = r[1];
            bb[2*j+1][0] = r[2]; bb[2*j+1][1] = r[3];
        }
#pragma unroll
        for (int mf = 0; mf < 3; mf++)
#pragma unroll
            for (int nf = 0; nf < 8; nf++)
                mma_f16(acc[mf][nf], a[mf], bb[nf][0], bb[nf][1]);
    }
}

// ================= zp + prep kernel (launch 0) ==============================
#define PREP_N 1440
#define ZP_N   (BATCH*C*4)
__global__ __launch_bounds__(256) void zp_prep_kernel(const float* __restrict__ wk,
                                                      const float* __restrict__ wv)
{
    int bid = blockIdx.x;
    if (bid < ZP_N) {
        size_t base = (size_t)bid * PLANE;
        for (int i = threadIdx.x; i < 260; i += 256) {
            if (i < 132) g_xp[base + i] = 0u;
            else         g_xp[base + (i - 131)*132] = 0u;
        }
    } else {
        int i = (bid - ZP_N) * 256 + threadIdx.x;
        if (i < KKDIM*C) {
            int k = i / C, oc = i % C;
            g_wkTh[i] = __float2half_rn(wk[oc*KKDIM + k]);
        } else {
            int j = i - KKDIM*C;
            if (j < C*C) {
                int ic = j / C, oc = j % C;
                g_wvTh[j] = __float2half_rn(wv[oc*C + ic]);
            }
        }
    }
}

// ================= sdq kernel (launches 1 and 2, halves) ====================
#define SDQ_N (16*BATCH*C)
__global__ __launch_bounds__(256) void sdq_kernel(int base,
                                                  const float* __restrict__ x,
                                                  const float* __restrict__ wq,
                                                  const float* __restrict__ wadw)
{
    __shared__ float xs[66][68];
    int bid = base + blockIdx.x;
    int tile = bid & 15;
    int bc   = bid >> 4;
    int c    = bc % C;
    int oy0 = (tile >> 2) * 32, ox0 = (tile & 3) * 32;
    int iy0 = 2*oy0 - 1, ix0 = 2*ox0 - 1;
    int ixA = ix0 + 1;
    const float* xp = x + (size_t)bc * NPIXF;
    int tid = threadIdx.x;

    for (int i = tid; i < 66*16; i += 256) {
        int r = i >> 4, seg = i & 15;
        int iy = iy0 + r;
        float4 v = make_float4(0.f, 0.f, 0.f, 0.f);
        if (iy >= 0 && iy < HW) v = *(const float4*)&xp[iy*HW + ixA + seg*4];
        *(float4*)&xs[r][seg*4] = v;
    }
    if (tid < 66) {
        int iy = iy0 + tid;
        float v = 0.f;
        if (iy >= 0 && iy < HW && ix0 >= 0) v = xp[iy*HW + ix0];
        xs[tid][64] = v;
    }
    __syncthreads();

    size_t pbase = (size_t)bc * 4 * PLANE;
    for (int i = tid; i < 4096; i += 256) {
        int ly = i >> 6, lx = i & 63;
        int ph = ((ly & 1) << 1) | (lx & 1);
        g_xp[pbase + (size_t)ph*PLANE + (oy0 + (ly>>1) + 1)*132 + ox0 + (lx>>1) + 1]
            = f2tf(xs[ly + 1][lx]);
    }

    float wqr[9], war[9];
#pragma unroll
    for (int i = 0; i < 9; i++) { wqr[i] = wq[c*9+i]; war[i] = wadw[c*9+i]; }
#pragma unroll
    for (int j = 0; j < 4; j++) {
        int oyl = (tid >> 5) + j*8, oxl = tid & 31;
        float aq = 0.f, aa = 0.f;
#pragma unroll
        for (int ky = 0; ky < 3; ky++)
#pragma unroll
            for (int kx = 0; kx < 3; kx++) {
                int cl = 2*oxl + kx;
                float v = (cl == 0) ? xs[2*oyl + ky][64] : xs[2*oyl + ky][cl - 1];
                aq = fmaf(wqr[ky*3+kx], v, aq);
                aa = fmaf(war[ky*3+kx], v, aa);
            }
        size_t o = (size_t)bc * NPIX + (oy0 + oyl)*HO + ox0 + oxl;
        g_q[o] = aq;
        g_adw[o] = aa;
    }
}

// ================= kconv body: fp16 pipelined implicit GEMM =================
// B register-staged from f32 planes: thread -> row kk = tid>>3, pixel-row pr = tid&7,
// 16 contiguous cols. Hybrid LDG.128/LDG.32 by rowoff alignment. A via cp.async.
__device__ __forceinline__ void kconv_ldB(float* tb, const int* rowoff, int k0, int tid)
{
    int ro = rowoff[k0 + (tid >> 3)] + (tid & 7)*132;
    const unsigned* gp = &g_xp[ro];
    if ((ro & 3) == 0) {
#pragma unroll
        for (int u = 0; u < 4; u++) {
            float4 v = *(const float4*)(gp + u*4);
            tb[u*4+0] = v.x; tb[u*4+1] = v.y; tb[u*4+2] = v.z; tb[u*4+3] = v.w;
        }
    } else {
#pragma unroll
        for (int u = 0; u < 16; u++) tb[u] = __uint_as_float(gp[u]);
    }
}
__device__ __forceinline__ void kconv_stB(__half* dst, const float* tb, int tid)
{
    __half2 h[8];
#pragma unroll
    for (int u = 0; u < 8; u++) h[u] = __floats2half2_rn(tb[2*u], tb[2*u+1]);
    uint4* d = (uint4*)&dst[(tid >> 3)*BPITCH + (tid & 7)*16];
    d[0] = *(uint4*)&h[0];
    d[1] = *(uint4*)&h[4];
}

__device__ void kconv_body(int bid)
{
    extern __shared__ char smc[];
    __half* A0 = (__half*)smc;
    __half* B0 = A0 + 2*ABUF;
    int* rowoff = (int*)(B0 + 2*BBUF);

    int b = bid >> 7;
    int tile = bid & 127;
    int oy0 = (tile >> 3) * 8, ox0 = (tile & 7) * 16;
    int tid = threadIdx.x;
    int warp = tid >> 5, lane = tid & 31;
    int wm = warp >> 1, wn = warp & 1;
    int g = lane >> 2, tg = lane & 3;

    for (int k = tid; k < KKDIM; k += 256) {
        int ic = k / 9, t = k - ic*9;
        int ky = t / 3, kx = t - ky*3;
        int py = (ky == 1) ? 0 : 1, px = (kx == 1) ? 0 : 1;
        int dy = (ky == 0) ? 0 : 1, dx = (kx == 0) ? 0 : 1;
        rowoff[k] = ((b*C + ic)*4 + py*2 + px)*PLANE + (oy0+dy)*132 + (ox0+dx);
    }
    __syncthreads();

    float acc[3][8][4];
#pragma unroll
    for (int mf = 0; mf < 3; mf++)
#pragma unroll
        for (int nf = 0; nf < 8; nf++)
#pragma unroll
            for (int q = 0; q < 4; q++) acc[mf][nf][q] = 0.f;

    // prologue: A chunk0 cp.async; B chunk0 synchronous
    for (int i = tid; i < 768; i += 256) {
        int kk = i / 24, seg = i % 24;
        cpa16(&A0[kk*APITCH + seg*8], &g_wkTh[kk*C + seg*8]);
    }
    CP_COMMIT;
    {
        float tb0[16];
        kconv_ldB(tb0, rowoff, 0, tid);
        kconv_stB(B0, tb0, tid);
    }

    float tb[16];
#pragma unroll 1
    for (int c2 = 0; c2 < 54; c2++) {
        int p = c2 & 1;
        int q2 = p ^ 1;
        if (c2 + 1 < 54) {
            int k0 = (c2 + 1) * 32;
            for (int i = tid; i < 768; i += 256) {
                int kk = i / 24, seg = i % 24;
                cpa16(&A0[q2*ABUF + kk*APITCH + seg*8], &g_wkTh[(k0+kk)*C + seg*8]);
            }
            CP_COMMIT;
            kconv_ldB(tb, rowoff, k0, tid);
            asm volatile("cp.async.wait_group 1;");
        } else {
            asm volatile("cp.async.wait_group 0;");
        }
        __syncthreads();
        mma_chunk(&A0[p*ABUF], &B0[p*BBUF], acc, wm, wn, lane);
        if (c2 + 1 < 54) kconv_stB(&B0[q2*BBUF], tb, tid);
        __syncthreads();
    }

#pragma unroll
    for (int mf = 0; mf < 3; mf++)
#pragma unroll
        for (int nf = 0; nf < 8; nf++) {
            int m = wm*48 + mf*16 + g;
            int n = wn*64 + nf*8 + tg*2;
            int oy = oy0 + (n >> 4), ox = ox0 + (n & 15);
            *(float2*)&g_k[(size_t)(b*C + m)*NPIX + oy*HO + ox] =
                make_float2(acc[mf][nf][0], acc[mf][nf][1]);
            *(float2*)&g_k[(size_t)(b*C + m + 8)*NPIX + oy*HO + ox] =
                make_float2(acc[mf][nf][2], acc[mf][nf][3]);
        }
}

// ================= tgemm body: M=192 x N=128, K=192 (fp16 core) =============
// MODE 0: B = x (f32 staged->half); out -> g_vh (half) * illu
// MODE 1: B = g_vh (half, cp.async); out -> fp32
template<int MODE>
__device__ void tgemm_body(int bid, const float* __restrict__ xin,
                           const float* __restrict__ illu,
                           float* __restrict__ outp)
{
    extern __shared__ char smc[];
    __half* A0 = (__half*)smc;
    __half* B0 = A0 + 2*ABUF;

    int b = bid >> 9;
    int n0 = (bid & 511) * 128;
    const __half* A = (MODE == 0) ? g_wvTh : (g_weffTh + (size_t)b*C*C);
    const float* Bf = (MODE == 0) ? (xin + (size_t)b*C*NPIXF) : nullptr;
    const __half* Bu = (MODE == 1) ? (g_vh + (size_t)b*C*NPIXF) : nullptr;
    const float* Ib = (MODE == 0) ? (illu + (size_t)b*C*NPIXF) : nullptr;

    int tid = threadIdx.x;
    int warp = tid >> 5, lane = tid & 31;
    int wm = warp >> 1, wn = warp & 1;
    int g = lane >> 2, tg = lane & 3;

    float acc[3][8][4];
#pragma unroll
    for (int mf = 0; mf < 3; mf++)
#pragma unroll
        for (int nf = 0; nf < 8; nf++)
#pragma unroll
            for (int q = 0; q < 4; q++) acc[mf][nf][q] = 0.f;

    // prologue
    for (int i = tid; i < 768; i += 256) {
        int kk = i / 24, seg = i % 24;
        cpa16(&A0[kk*APITCH + seg*8], &A[kk*C + seg*8]);
    }
    if (MODE == 1) {
        for (int i = tid; i < 512; i += 256) {
            int kk = i >> 4, seg = i & 15;
            cpa16(&B0[kk*BPITCH + seg*8], &Bu[(size_t)kk*NPIXF + n0 + seg*8]);
        }
    }
    CP_COMMIT;
    if (MODE == 0) {
#pragma unroll
        for (int j = 0; j < 4; j++) {
            int i = tid + j*256;
            int kk = i >> 5, n4 = (i & 31) * 4;
            float4 t = *(const float4*)&Bf[(size_t)kk*NPIXF + n0 + n4];
            __half2 h01 = __floats2half2_rn(t.x, t.y);
            __half2 h23 = __floats2half2_rn(t.z, t.w);
            *(uint2*)&B0[kk*BPITCH + n4] = make_uint2(*(unsigned*)&h01, *(unsigned*)&h23);
        }
    }

    float4 tmpf[4];
#pragma unroll 1
    for (int c2 = 0; c2 < 6; c2++) {
        int p = c2 & 1;
        int q2 = p ^ 1;
        if (c2 + 1 < 6) {
            int k0 = (c2 + 1) * 32;
            for (int i = tid; i < 768; i += 256) {
                int kk = i / 24, seg = i % 24;
                cpa16(&A0[q2*ABUF + kk*APITCH + seg*8], &A[(k0+kk)*C + seg*8]);
            }
            if (MODE == 1) {
                for (int i = tid; i < 512; i += 256) {
                    int kk = i >> 4, seg = i & 15;
                    cpa16(&B0[q2*BBUF + kk*BPITCH + seg*8],
                          &Bu[(size_t)(k0+kk)*NPIXF + n0 + seg*8]);
                }
            }
            CP_COMMIT;
            if (MODE == 0) {
#pragma unroll
                for (int j = 0; j < 4; j++) {
                    int i = tid + j*256;
                    int kk = i >> 5, n4 = (i & 31) * 4;
                    tmpf[j] = *(const float4*)&Bf[(size_t)(k0+kk)*NPIXF + n0 + n4];
                }
            }
            asm volatile("cp.async.wait_group 1;");
        } else {
            asm volatile("cp.async.wait_group 0;");
        }
        __syncthreads();
        mma_chunk(&A0[p*ABUF], &B0[p*BBUF], acc, wm, wn, lane);
        if (MODE == 0 && c2 + 1 < 6) {
#pragma unroll
            for (int j = 0; j < 4; j++) {
                int i = tid + j*256;
                int kk = i >> 5, n4 = (i & 31) * 4;
                __half2 h01 = __floats2half2_rn(tmpf[j].x, tmpf[j].y);
                __half2 h23 = __floats2half2_rn(tmpf[j].z, tmpf[j].w);
                *(uint2*)&B0[q2*BBUF + kk*BPITCH + n4] =
                    make_uint2(*(unsigned*)&h01, *(unsigned*)&h23);
            }
        }
        __syncthreads();
    }

#pragma unroll
    for (int mf = 0; mf < 3; mf++)
#pragma unroll
        for (int nf = 0; nf < 8; nf++) {
            int m = wm*48 + mf*16 + g;
            int n = n0 + wn*64 + nf*8 + tg*2;
            if (MODE == 0) {
                float2 i0 = *(const float2*)&Ib[(size_t)m*NPIXF + n];
                float2 i1 = *(const float2*)&Ib[(size_t)(m+8)*NPIXF + n];
                __half* O = g_vh + (size_t)b*C*NPIXF;
                *(__half2*)&O[(size_t)m*NPIXF + n] =
                    __floats2half2_rn(acc[mf][nf][0]*i0.x, acc[mf][nf][1]*i0.y);
                *(__half2*)&O[(size_t)(m+8)*NPIXF + n] =
                    __floats2half2_rn(acc[mf][nf][2]*i1.x, acc[mf][nf][3]*i1.y);
            } else {
                float* O = outp + (size_t)b*C*NPIXF;
                *(float2*)&O[(size_t)m*NPIXF + n] =
                    make_float2(acc[mf][nf][0], acc[mf][nf][1]);
                *(float2*)&O[(size_t)(m+8)*NPIXF + n] =
                    make_float2(acc[mf][nf][2], acc[mf][nf][3]);
            }
        }
}

// ================= apw body: pointwise 192->96 (+bias) ======================
__device__ void apw_body(int bid, const float* __restrict__ wapw,
                         const float* __restrict__ bapw)
{
    extern __shared__ char smc[];
    float* s = (float*)smc;
    int b = bid >> 8;
    int p0 = (bid & 255) * 64;
    for (int i = threadIdx.x; i < C*64; i += 256) {
        int cc = i >> 6, pp = i & 63;
        s[i] = g_adw[(size_t)(b*C + cc)*NPIX + p0 + pp];
    }
    __syncthreads();
    int pg  = threadIdx.x & 15;
    int ocb = threadIdx.x >> 4;
    for (int oc = ocb; oc < CA; oc += 16) {
        float bsv = bapw[oc];
        float4 acc = make_float4(bsv, bsv, bsv, bsv);
        for (int ic = 0; ic < C; ic++) {
            float w = __ldg(&wapw[oc*C + ic]);
            float4 xv = *reinterpret_cast<const float4*>(&s[ic*64 + pg*4]);
            acc.x = fmaf(w, xv.x, acc.x);
            acc.y = fmaf(w, xv.y, acc.y);
            acc.z = fmaf(w, xv.z, acc.z);
            acc.w = fmaf(w, xv.w, acc.w);
        }
        *reinterpret_cast<float4*>(&g_a[(size_t)(b*CA + oc)*NPIX + p0 + pg*4]) = acc;
    }
}

// ================= fat kernel (launch index 3) ==============================
#define KCONV_N 512
#define TG0_N   2048
#define APW_N   1024
__global__ __launch_bounds__(256) void fat_kernel(const float* __restrict__ x,
                                                  const float* __restrict__ illu,
                                                  const float* __restrict__ wapw,
                                                  const float* __restrict__ bapw)
{
    int bid = blockIdx.x;
    if (bid < KCONV_N)            kconv_body(bid);
    else if (bid < KCONV_N+TG0_N) tgemm_body<0>(bid - KCONV_N, x, illu, nullptr);
    else                          apw_body(bid - KCONV_N - TG0_N, wapw, bapw);
}

__global__ __launch_bounds__(256) void tgemm1_kernel(float* __restrict__ outp)
{
    tgemm_body<1>(blockIdx.x, nullptr, nullptr, outp);
}

// ================= attention dots + fused norms =============================
__global__ __launch_bounds__(768) void attn_kernel()
{
    __shared__ float a_s[CAH][256];
    int split = blockIdx.x, bh = blockIdx.y;
    int b = bh >> 3, h = bh & 7;
    int tid = threadIdx.x, warp = tid >> 5, lane = tid & 31;
    const float* qp = g_q + (size_t)(b*C + h*CQH + warp)*NPIX;
    const float* kp = g_k + (size_t)(b*C + h*CQH + warp)*NPIX;
    const float* ap = g_a + (size_t)(b*CA + h*CAH)*NPIX;
    int p0 = split * (NPIX / NSPLIT);

    float dq[12], dk[12];
#pragma unroll
    for (int d = 0; d < 12; d++) { dq[d] = 0.f; dk[d] = 0.f; }
    float qq = 0.f, kk = 0.f, aa = 0.f;

    for (int c0 = 0; c0 < NPIX/NSPLIT; c0 += 256) {
        for (int i = tid; i < CAH*256; i += 768) {
            int d = i >> 8, p = i & 255;
            a_s[d][p] = ap[(size_t)d*NPIX + p0 + c0 + p];
        }
        __syncthreads();
#pragma unroll
        for (int hf = 0; hf < 2; hf++) {
            int p = hf*128 + lane*4;
            float4 qv = *(const float4*)&qp[p0 + c0 + p];
            float4 kv = *(const float4*)&kp[p0 + c0 + p];
            qq += qv.x*qv.x + qv.y*qv.y + qv.z*qv.z + qv.w*qv.w;
            kk += kv.x*kv.x + kv.y*kv.y + kv.z*kv.z + kv.w*kv.w;
            if (warp < CAH) {
                float4 av = *(const float4*)&a_s[warp][p];
                aa += av.x*av.x + av.y*av.y + av.z*av.z + av.w*av.w;
            }
#pragma unroll
            for (int d = 0; d < 12; d++) {
                float4 av = *(const float4*)&a_s[d][p];
                dq[d] += qv.x*av.x + qv.y*av.y + qv.z*av.z + qv.w*av.w;
                dk[d] += kv.x*av.x + kv.y*av.y + kv.z*av.z + kv.w*av.w;
            }
        }
        __syncthreads();
    }
#pragma unroll
    for (int off = 16; off; off >>= 1) {
#pragma unroll
        for (int d = 0; d < 12; d++) {
            dq[d] += __shfl_down_sync(0xffffffffu, dq[d], off);
            dk[d] += __shfl_down_sync(0xffffffffu, dk[d], off);
        }
        qq += __shfl_down_sync(0xffffffffu, qq, off);
        kk += __shfl_down_sync(0xffffffffu, kk, off);
        aa += __shfl_down_sync(0xffffffffu, aa, off);
    }
    if (lane == 0) {
        float* out = &g_dotp[((size_t)split*BATCH*HEADS + bh)*DOTP];
#pragma unroll
        for (int d = 0; d < 12; d++) {
            out[warp*12 + d]       = dq[d];
            out[288 + warp*12 + d] = dk[d];
        }
        out[576 + warp] = qq;
        out[600 + warp] = kk;
        if (warp < 12) out[624 + warp] = aa;
    }
}

// ================= combine: norms, softmax, M, W_eff^T slice (half) =========
#define WSLICE (C*C/64)      // 576
__global__ __launch_bounds__(256) void combine_kernel(const float* __restrict__ wo,
                                                      const float* __restrict__ ta,
                                                      const float* __restrict__ tv)
{
    __shared__ float buf[HEADS*DOTP];
    __shared__ float SA[HEADS][CQH][CAH];
    __shared__ float SK[HEADS][CAH][CQH];
    int slice = blockIdx.x, b = blockIdx.y, tid = threadIdx.x;

    for (int i = tid; i < HEADS*DOTP; i += 256) {
        int h = i / DOTP, e = i - h*DOTP;
        float s = 0.f;
#pragma unroll
        for (int sp = 0; sp < NSPLIT; sp++)
            s += g_dotp[((size_t)sp*BATCH*HEADS + b*HEADS + h)*DOTP + e];
        buf[i] = s;
    }
    __syncthreads();

    if (tid < HEADS*CQH) {
        int h = tid / CQH, c = tid % CQH;
        const float* B = &buf[h*DOTP];
        float invq = 1.f / fmaxf(sqrtf(B[576 + c]), 1e-12f);
        float tah = ta[h];
        float l[CAH], m = -1e30f;
#pragma unroll
        for (int d = 0; d < CAH; d++) {
            float inva = 1.f / fmaxf(sqrtf(B[624 + d]), 1e-12f);
            l[d] = B[c*12 + d] * invq * inva * tah;
            m = fmaxf(m, l[d]);
        }
        float s = 0.f;
#pragma unroll
        for (int d = 0; d < CAH; d++) { l[d] = expf(l[d] - m); s += l[d]; }
        float inv = 1.f / s;
#pragma unroll
        for (int d = 0; d < CAH; d++) SA[h][c][d] = l[d] * inv;
    }
    if (tid < HEADS*CAH) {
        int h = tid / CAH, d = tid % CAH;
        const float* B = &buf[h*DOTP];
        float inva = 1.f / fmaxf(sqrtf(B[624 + d]), 1e-12f);
        float tvh = tv[h];
        float l[CQH], m = -1e30f;
#pragma unroll
        for (int c = 0; c < CQH; c++) {
            float invk = 1.f / fmaxf(sqrtf(B[600 + c]), 1e-12f);
            l[c] = B[288 + c*12 + d] * invk * inva * tvh;
            m = fmaxf(m, l[c]);
        }
        float s = 0.f;
#pragma unroll
        for (int c = 0; c < CQH; c++) { l[c] = expf(l[c] - m); s += l[c]; }
        float inv = 1.f / s;
#pragma unroll
        for (int c = 0; c < CQH; c++) SK[h][d][c] = l[c] * inv;
    }
    __syncthreads();

    float* M = buf;
    for (int i = tid; i < HEADS*CQH*CQH; i += 256) {
        int h = i / (CQH*CQH), r = (i / CQH) % CQH, j = i % CQH;
        float s = 0.f;
#pragma unroll
        for (int d = 0; d < CAH; d++) s = fmaf(SA[h][r][d], SK[h][d][j], s);
        M[(h*CQH + r)*CQH + j] = s;
    }
    __syncthreads();

    int base = slice * WSLICE;
    for (int i = base + tid; i < base + WSLICE; i += 256) {
        int cv = i / C, o = i % C;
        int hv = cv / CQH, j = cv % CQH;
        float s = 0.f;
#pragma unroll
        for (int k = 0; k < CQH; k++)
            s = fmaf(wo[o*C + hv*CQH + k], M[(hv*CQH + k)*CQH + j], s);
        g_weffTh[(size_t)b*C*C + i] = __float2half_rn(s);
    }
}

// ================= launch ===================================================
extern "C" void kernel_launch(void* const* d_in, const int* in_sizes, int n_in,
                              void* d_out, int out_size)
{
    const float* x    = (const float*)d_in[0];
    const float* illu = (const float*)d_in[1];
    const float* wq   = (const float*)d_in[2];
    const float* wk   = (const float*)d_in[3];
    const float* wadw = (const float*)d_in[4];
    const float* wapw = (const float*)d_in[5];
    const float* bapw = (const float*)d_in[6];
    const float* wv   = (const float*)d_in[7];
    const float* wo   = (const float*)d_in[8];
    const float* ta   = (const float*)d_in[9];
    const float* tv   = (const float*)d_in[10];
    float* out = (float*)d_out;

    const int fat_smem = (2*ABUF + 2*BBUF)*2 + KKDIM*4;   // 49920
    const int tg_smem  = (2*ABUF + 2*BBUF)*2;             // 43008
    cudaFuncSetAttribute(fat_kernel, cudaFuncAttributeMaxDynamicSharedMemorySize, fat_smem);
    cudaFuncSetAttribute(tgemm1_kernel, cudaFuncAttributeMaxDynamicSharedMemorySize, tg_smem);

    zp_prep_kernel<<<ZP_N + PREP_N, 256>>>(wk, wv);
    sdq_kernel    <<<SDQ_N/2, 256>>>(0,        x, wq, wadw);
    sdq_kernel    <<<SDQ_N/2, 256>>>(SDQ_N/2,  x, wq, wadw);
    fat_kernel    <<<KCONV_N + TG0_N + APW_N, 256, fat_smem>>>(x, illu, wapw, bapw);
    attn_kernel   <<<dim3(NSPLIT, BATCH*HEADS), 768>>>();
    combine_kernel<<<dim3(64, BATCH), 256>>>(wo, ta, tv);
    tgemm1_kernel <<<TG0_N, 256, tg_smem>>>(out);
}

// round 15
// speedup vs baseline: 1.2497x; 1.0737x over previous
#include <cuda_runtime.h>
#include <cuda_fp16.h>
#include <cstdint>

#define BATCH 4
#define C 192
#define HW 256
#define HO 128
#define NPIX (HO*HO)      // 16384
#define NPIXF (HW*HW)     // 65536
#define HEADS 8
#define CQH 24
#define CAH 12
#define CA 96
#define KKDIM (C*9)       // 1728
#define PLANE (129*132)
#define NSPLIT 16
#define DOTP 640
#define APITCH 200        // halves
#define BPITCH 136        // halves
#define ABUF (32*APITCH)  // 6400 halves
#define BBUF (32*BPITCH)  // 4352 halves

// ---------------- scratch ----------------
__device__ float    g_q[BATCH*C*NPIX];
__device__ float    g_k[BATCH*C*NPIX];
__device__ float    g_adw[BATCH*C*NPIX];
__device__ float    g_a[BATCH*CA*NPIX];
__device__ __align__(16) __half g_vh[(size_t)BATCH*C*NPIXF];
__device__ unsigned g_xp[(size_t)BATCH*C*4*PLANE];            // tf32/f32 bits
__device__ __align__(16) __half g_wkTh[KKDIM*C];              // [k][oc]
__device__ __align__(16) __half g_wvTh[C*C];                  // [ic][oc]
__device__ __align__(16) __half g_weffTh[BATCH*C*C];          // [cv][o]
__device__ float    g_dotp[(size_t)NSPLIT*BATCH*HEADS*DOTP];

// ---------------- helpers ----------------
__device__ __forceinline__ unsigned f2tf(float f){
    unsigned r; asm("cvt.rna.tf32.f32 %0, %1;" : "=r"(r) : "f"(f)); return r;
}
__device__ __forceinline__ unsigned s2u(const void* p){
    return (unsigned)__cvta_generic_to_shared(p);
}
__device__ __forceinline__ void ldsm4t(unsigned* r, unsigned addr){
    asm volatile("ldmatrix.sync.aligned.m8n8.x4.trans.shared.b16 {%0,%1,%2,%3}, [%4];"
                 : "=r"(r[0]),"=r"(r[1]),"=r"(r[2]),"=r"(r[3]) : "r"(addr));
}
__device__ __forceinline__ void mma_f16(float* c, const unsigned* a, unsigned b0, unsigned b1){
    asm volatile("mma.sync.aligned.m16n8k16.row.col.f32.f16.f16.f32 "
                 "{%0,%1,%2,%3},{%4,%5,%6,%7},{%8,%9},{%0,%1,%2,%3};"
                 : "+f"(c[0]),"+f"(c[1]),"+f"(c[2]),"+f"(c[3])
                 : "r"(a[0]),"r"(a[1]),"r"(a[2]),"r"(a[3]),"r"(b0),"r"(b1));
}
__device__ __forceinline__ void cpa16(void* s, const void* g){
    unsigned sa = (unsigned)__cvta_generic_to_shared(s);
    asm volatile("cp.async.ca.shared.global [%0],[%1],16;" :: "r"(sa), "l"(g));
}
#define CP_COMMIT asm volatile("cp.async.commit_group;")

// fp16 MMA consumer: A_s[k][m] pitch APITCH, B_s[k][n] pitch BPITCH, K-chunk 32
__device__ __forceinline__ void mma_chunk(const __half* Ab, const __half* Bb,
                                          float acc[3][8][4], int wm, int wn, int lane)
{
    int aRow = (lane & 7) + ((lane & 16) ? 8 : 0);
    int aCol = wm*48 + ((lane & 8) ? 8 : 0);
    int bRow = (lane & 7) + ((lane & 8) ? 8 : 0);
    int bCol = wn*64 + ((lane & 16) ? 8 : 0);
    unsigned aBase = s2u(Ab), bBase = s2u(Bb);
#pragma unroll
    for (int ks = 0; ks < 2; ks++) {
        int kb = ks*16;
        unsigned a[3][4];
#pragma unroll
        for (int mf = 0; mf < 3; mf++)
            ldsm4t(a[mf], aBase + (unsigned)(((kb + aRow)*APITCH + aCol + mf*16)*2));
        unsigned bb[8][2];
#pragma unroll
        for (int j = 0; j < 4; j++) {
            unsigned r[4];
            ldsm4t(r, bBase + (unsigned)(((kb + bRow)*BPITCH + bCol + j*16)*2));
            bb[2*j][0] = r[0]; bb[2*j][1] = r[1];
            bb[2*j+1][0] = r[2]; bb[2*j+1][1] = r[3];
        }
#pragma unroll
        for (int mf = 0; mf < 3; mf++)
#pragma unroll
            for (int nf = 0; nf < 8; nf++)
                mma_f16(acc[mf][nf], a[mf], bb[nf][0], bb[nf][1]);
    }
}

// ================= zp + prep kernel (launch 0) ==============================
#define PREP_N 1440
#define ZP_N   (BATCH*C*4)
__global__ __launch_bounds__(256) void zp_prep_kernel(const float* __restrict__ wk,
                                                      const float* __restrict__ wv)
{
    int bid = blockIdx.x;
    if (bid < ZP_N) {
        size_t base = (size_t)bid * PLANE;
        for (int i = threadIdx.x; i < 260; i += 256) {
            if (i < 132) g_xp[base + i] = 0u;
            else         g_xp[base + (i - 131)*132] = 0u;
        }
    } else {
        int i = (bid - ZP_N) * 256 + threadIdx.x;
        if (i < KKDIM*C) {
            int k = i / C, oc = i % C;
            g_wkTh[i] = __float2half_rn(wk[oc*KKDIM + k]);
        } else {
            int j = i - KKDIM*C;
            if (j < C*C) {
                int ic = j / C, oc = j % C;
                g_wvTh[j] = __float2half_rn(wv[oc*C + ic]);
            }
        }
    }
}

// ================= sdq kernel (launches 1 and 2, halves) ====================
#define SDQ_N (16*BATCH*C)
__global__ __launch_bounds__(256) void sdq_kernel(int base,
                                                  const float* __restrict__ x,
                                                  const float* __restrict__ wq,
                                                  const float* __restrict__ wadw)
{
    __shared__ float xs[66][68];
    int bid = base + blockIdx.x;
    int tile = bid & 15;
    int bc   = bid >> 4;
    int c    = bc % C;
    int oy0 = (tile >> 2) * 32, ox0 = (tile & 3) * 32;
    int iy0 = 2*oy0 - 1, ix0 = 2*ox0 - 1;
    int ixA = ix0 + 1;
    const float* xp = x + (size_t)bc * NPIXF;
    int tid = threadIdx.x;

    for (int i = tid; i < 66*16; i += 256) {
        int r = i >> 4, seg = i & 15;
        int iy = iy0 + r;
        float4 v = make_float4(0.f, 0.f, 0.f, 0.f);
        if (iy >= 0 && iy < HW) v = *(const float4*)&xp[iy*HW + ixA + seg*4];
        *(float4*)&xs[r][seg*4] = v;
    }
    if (tid < 66) {
        int iy = iy0 + tid;
        float v = 0.f;
        if (iy >= 0 && iy < HW && ix0 >= 0) v = xp[iy*HW + ix0];
        xs[tid][64] = v;
    }
    __syncthreads();

    size_t pbase = (size_t)bc * 4 * PLANE;
    for (int i = tid; i < 4096; i += 256) {
        int ly = i >> 6, lx = i & 63;
        int ph = ((ly & 1) << 1) | (lx & 1);
        g_xp[pbase + (size_t)ph*PLANE + (oy0 + (ly>>1) + 1)*132 + ox0 + (lx>>1) + 1]
            = f2tf(xs[ly + 1][lx]);
    }

    float wqr[9], war[9];
#pragma unroll
    for (int i = 0; i < 9; i++) { wqr[i] = wq[c*9+i]; war[i] = wadw[c*9+i]; }
#pragma unroll
    for (int j = 0; j < 4; j++) {
        int oyl = (tid >> 5) + j*8, oxl = tid & 31;
        float aq = 0.f, aa = 0.f;
#pragma unroll
        for (int ky = 0; ky < 3; ky++)
#pragma unroll
            for (int kx = 0; kx < 3; kx++) {
                int cl = 2*oxl + kx;
                float v = (cl == 0) ? xs[2*oyl + ky][64] : xs[2*oyl + ky][cl - 1];
                aq = fmaf(wqr[ky*3+kx], v, aq);
                aa = fmaf(war[ky*3+kx], v, aa);
            }
        size_t o = (size_t)bc * NPIX + (oy0 + oyl)*HO + ox0 + oxl;
        g_q[o] = aq;
        g_adw[o] = aa;
    }
}

// ================= kconv body: fp16 pipelined implicit GEMM =================
__device__ __forceinline__ void kconv_ldB(float* tb, const int* rowoff, int k0, int tid)
{
    int ro = rowoff[k0 + (tid >> 3)] + (tid & 7)*132;
    const unsigned* gp = &g_xp[ro];
    if ((ro & 3) == 0) {
#pragma unroll
        for (int u = 0; u < 4; u++) {
            float4 v = *(const float4*)(gp + u*4);
            tb[u*4+0] = v.x; tb[u*4+1] = v.y; tb[u*4+2] = v.z; tb[u*4+3] = v.w;
        }
    } else {
#pragma unroll
        for (int u = 0; u < 16; u++) tb[u] = __uint_as_float(gp[u]);
    }
}
__device__ __forceinline__ void kconv_stB(__half* dst, const float* tb, int tid)
{
    __half2 h[8];
#pragma unroll
    for (int u = 0; u < 8; u++) h[u] = __floats2half2_rn(tb[2*u], tb[2*u+1]);
    uint4* d = (uint4*)&dst[(tid >> 3)*BPITCH + (tid & 7)*16];
    d[0] = *(uint4*)&h[0];
    d[1] = *(uint4*)&h[4];
}

__device__ void kconv_body(int bid)
{
    extern __shared__ char smc[];
    __half* A0 = (__half*)smc;
    __half* B0 = A0 + 2*ABUF;
    int* rowoff = (int*)(B0 + 2*BBUF);

    int b = bid >> 7;
    int tile = bid & 127;
    int oy0 = (tile >> 3) * 8, ox0 = (tile & 7) * 16;
    int tid = threadIdx.x;
    int warp = tid >> 5, lane = tid & 31;
    int wm = warp >> 1, wn = warp & 1;
    int g = lane >> 2, tg = lane & 3;

    for (int k = tid; k < KKDIM; k += 256) {
        int ic = k / 9, t = k - ic*9;
        int ky = t / 3, kx = t - ky*3;
        int py = (ky == 1) ? 0 : 1, px = (kx == 1) ? 0 : 1;
        int dy = (ky == 0) ? 0 : 1, dx = (kx == 0) ? 0 : 1;
        rowoff[k] = ((b*C + ic)*4 + py*2 + px)*PLANE + (oy0+dy)*132 + (ox0+dx);
    }
    __syncthreads();

    float acc[3][8][4];
#pragma unroll
    for (int mf = 0; mf < 3; mf++)
#pragma unroll
        for (int nf = 0; nf < 8; nf++)
#pragma unroll
            for (int q = 0; q < 4; q++) acc[mf][nf][q] = 0.f;

    for (int i = tid; i < 768; i += 256) {
        int kk = i / 24, seg = i % 24;
        cpa16(&A0[kk*APITCH + seg*8], &g_wkTh[kk*C + seg*8]);
    }
    CP_COMMIT;
    {
        float tb0[16];
        kconv_ldB(tb0, rowoff, 0, tid);
        kconv_stB(B0, tb0, tid);
    }

    float tb[16];
#pragma unroll 1
    for (int c2 = 0; c2 < 54; c2++) {
        int p = c2 & 1;
        int q2 = p ^ 1;
        if (c2 + 1 < 54) {
            int k0 = (c2 + 1) * 32;
            for (int i = tid; i < 768; i += 256) {
                int kk = i / 24, seg = i % 24;
                cpa16(&A0[q2*ABUF + kk*APITCH + seg*8], &g_wkTh[(k0+kk)*C + seg*8]);
            }
            CP_COMMIT;
            kconv_ldB(tb, rowoff, k0, tid);
            asm volatile("cp.async.wait_group 1;");
        } else {
            asm volatile("cp.async.wait_group 0;");
        }
        __syncthreads();
        mma_chunk(&A0[p*ABUF], &B0[p*BBUF], acc, wm, wn, lane);
        if (c2 + 1 < 54) kconv_stB(&B0[q2*BBUF], tb, tid);
        __syncthreads();
    }

#pragma unroll
    for (int mf = 0; mf < 3; mf++)
#pragma unroll
        for (int nf = 0; nf < 8; nf++) {
            int m = wm*48 + mf*16 + g;
            int n = wn*64 + nf*8 + tg*2;
            int oy = oy0 + (n >> 4), ox = ox0 + (n & 15);
            *(float2*)&g_k[(size_t)(b*C + m)*NPIX + oy*HO + ox] =
                make_float2(acc[mf][nf][0], acc[mf][nf][1]);
            *(float2*)&g_k[(size_t)(b*C + m + 8)*NPIX + oy*HO + ox] =
                make_float2(acc[mf][nf][2], acc[mf][nf][3]);
        }
}

// ================= tgemm body: M=192 x N=128, K=192 (fp16 core) =============
template<int MODE>
__device__ void tgemm_body(int bid, const float* __restrict__ xin,
                           const float* __restrict__ illu,
                           float* __restrict__ outp)
{
    extern __shared__ char smc[];
    __half* A0 = (__half*)smc;
    __half* B0 = A0 + 2*ABUF;

    int b = bid >> 9;
    int n0 = (bid & 511) * 128;
    const __half* A = (MODE == 0) ? g_wvTh : (g_weffTh + (size_t)b*C*C);
    const float* Bf = (MODE == 0) ? (xin + (size_t)b*C*NPIXF) : nullptr;
    const __half* Bu = (MODE == 1) ? (g_vh + (size_t)b*C*NPIXF) : nullptr;
    const float* Ib = (MODE == 0) ? (illu + (size_t)b*C*NPIXF) : nullptr;

    int tid = threadIdx.x;
    int warp = tid >> 5, lane = tid & 31;
    int wm = warp >> 1, wn = warp & 1;
    int g = lane >> 2, tg = lane & 3;

    float acc[3][8][4];
#pragma unroll
    for (int mf = 0; mf < 3; mf++)
#pragma unroll
        for (int nf = 0; nf < 8; nf++)
#pragma unroll
            for (int q = 0; q < 4; q++) acc[mf][nf][q] = 0.f;

    for (int i = tid; i < 768; i += 256) {
        int kk = i / 24, seg = i % 24;
        cpa16(&A0[kk*APITCH + seg*8], &A[kk*C + seg*8]);
    }
    if (MODE == 1) {
        for (int i = tid; i < 512; i += 256) {
            int kk = i >> 4, seg = i & 15;
            cpa16(&B0[kk*BPITCH + seg*8], &Bu[(size_t)kk*NPIXF + n0 + seg*8]);
        }
    }
    CP_COMMIT;
    if (MODE == 0) {
#pragma unroll
        for (int j = 0; j < 4; j++) {
            int i = tid + j*256;
            int kk = i >> 5, n4 = (i & 31) * 4;
            float4 t = *(const float4*)&Bf[(size_t)kk*NPIXF + n0 + n4];
            __half2 h01 = __floats2half2_rn(t.x, t.y);
            __half2 h23 = __floats2half2_rn(t.z, t.w);
            *(uint2*)&B0[kk*BPITCH + n4] = make_uint2(*(unsigned*)&h01, *(unsigned*)&h23);
        }
    }

    float4 tmpf[4];
#pragma unroll 1
    for (int c2 = 0; c2 < 6; c2++) {
        int p = c2 & 1;
        int q2 = p ^ 1;
        if (c2 + 1 < 6) {
            int k0 = (c2 + 1) * 32;
            for (int i = tid; i < 768; i += 256) {
                int kk = i / 24, seg = i % 24;
                cpa16(&A0[q2*ABUF + kk*APITCH + seg*8], &A[(k0+kk)*C + seg*8]);
            }
            if (MODE == 1) {
                for (int i = tid; i < 512; i += 256) {
                    int kk = i >> 4, seg = i & 15;
                    cpa16(&B0[q2*BBUF + kk*BPITCH + seg*8],
                          &Bu[(size_t)(k0+kk)*NPIXF + n0 + seg*8]);
                }
            }
            CP_COMMIT;
            if (MODE == 0) {
#pragma unroll
                for (int j = 0; j < 4; j++) {
                    int i = tid + j*256;
                    int kk = i >> 5, n4 = (i & 31) * 4;
                    tmpf[j] = *(const float4*)&Bf[(size_t)(k0+kk)*NPIXF + n0 + n4];
                }
            }
            asm volatile("cp.async.wait_group 1;");
        } else {
            asm volatile("cp.async.wait_group 0;");
        }
        __syncthreads();
        mma_chunk(&A0[p*ABUF], &B0[p*BBUF], acc, wm, wn, lane);
        if (MODE == 0 && c2 + 1 < 6) {
#pragma unroll
            for (int j = 0; j < 4; j++) {
                int i = tid + j*256;
                int kk = i >> 5, n4 = (i & 31) * 4;
                __half2 h01 = __floats2half2_rn(tmpf[j].x, tmpf[j].y);
                __half2 h23 = __floats2half2_rn(tmpf[j].z, tmpf[j].w);
                *(uint2*)&B0[q2*BBUF + kk*BPITCH + n4] =
                    make_uint2(*(unsigned*)&h01, *(unsigned*)&h23);
            }
        }
        __syncthreads();
    }

#pragma unroll
    for (int mf = 0; mf < 3; mf++)
#pragma unroll
        for (int nf = 0; nf < 8; nf++) {
            int m = wm*48 + mf*16 + g;
            int n = n0 + wn*64 + nf*8 + tg*2;
            if (MODE == 0) {
                float2 i0 = *(const float2*)&Ib[(size_t)m*NPIXF + n];
                float2 i1 = *(const float2*)&Ib[(size_t)(m+8)*NPIXF + n];
                __half* O = g_vh + (size_t)b*C*NPIXF;
                *(__half2*)&O[(size_t)m*NPIXF + n] =
                    __floats2half2_rn(acc[mf][nf][0]*i0.x, acc[mf][nf][1]*i0.y);
                *(__half2*)&O[(size_t)(m+8)*NPIXF + n] =
                    __floats2half2_rn(acc[mf][nf][2]*i1.x, acc[mf][nf][3]*i1.y);
            } else {
                float* O = outp + (size_t)b*C*NPIXF;
                *(float2*)&O[(size_t)m*NPIXF + n] =
                    make_float2(acc[mf][nf][0], acc[mf][nf][1]);
                *(float2*)&O[(size_t)(m+8)*NPIXF + n] =
                    make_float2(acc[mf][nf][2], acc[mf][nf][3]);
            }
        }
}

// ================= apw body: pointwise 192->96 (+bias) ======================
__device__ void apw_body(int bid, const float* __restrict__ wapw,
                         const float* __restrict__ bapw)
{
    extern __shared__ char smc[];
    float* s = (float*)smc;
    int b = bid >> 8;
    int p0 = (bid & 255) * 64;
    for (int i = threadIdx.x; i < C*64; i += 256) {
        int cc = i >> 6, pp = i & 63;
        s[i] = g_adw[(size_t)(b*C + cc)*NPIX + p0 + pp];
    }
    __syncthreads();
    int pg  = threadIdx.x & 15;
    int ocb = threadIdx.x >> 4;
    for (int oc = ocb; oc < CA; oc += 16) {
        float bsv = bapw[oc];
        float4 acc = make_float4(bsv, bsv, bsv, bsv);
        for (int ic = 0; ic < C; ic++) {
            float w = __ldg(&wapw[oc*C + ic]);
            float4 xv = *reinterpret_cast<const float4*>(&s[ic*64 + pg*4]);
            acc.x = fmaf(w, xv.x, acc.x);
            acc.y = fmaf(w, xv.y, acc.y);
            acc.z = fmaf(w, xv.z, acc.z);
            acc.w = fmaf(w, xv.w, acc.w);
        }
        *reinterpret_cast<float4*>(&g_a[(size_t)(b*CA + oc)*NPIX + p0 + pg*4]) = acc;
    }
}

// ================= fat kernel (launch index 3, forced 2 CTA/SM) =============
#define KCONV_N 512
#define TG0_N   2048
#define APW_N   1024
__global__ __launch_bounds__(256, 2) void fat_kernel(const float* __restrict__ x,
                                                     const float* __restrict__ illu,
                                                     const float* __restrict__ wapw,
                                                     const float* __restrict__ bapw)
{
    int bid = blockIdx.x;
    if (bid < KCONV_N)            kconv_body(bid);
    else if (bid < KCONV_N+TG0_N) tgemm_body<0>(bid - KCONV_N, x, illu, nullptr);
    else                          apw_body(bid - KCONV_N - TG0_N, wapw, bapw);
}

__global__ __launch_bounds__(256, 2) void tgemm1_kernel(float* __restrict__ outp)
{
    tgemm_body<1>(blockIdx.x, nullptr, nullptr, outp);
}

// ================= attention dots + fused norms =============================
__global__ __launch_bounds__(768) void attn_kernel()
{
    __shared__ float a_s[CAH][256];
    int split = blockIdx.x, bh = blockIdx.y;
    int b = bh >> 3, h = bh & 7;
    int tid = threadIdx.x, warp = tid >> 5, lane = tid & 31;
    const float* qp = g_q + (size_t)(b*C + h*CQH + warp)*NPIX;
    const float* kp = g_k + (size_t)(b*C + h*CQH + warp)*NPIX;
    const float* ap = g_a + (size_t)(b*CA + h*CAH)*NPIX;
    int p0 = split * (NPIX / NSPLIT);

    float dq[12], dk[12];
#pragma unroll
    for (int d = 0; d < 12; d++) { dq[d] = 0.f; dk[d] = 0.f; }
    float qq = 0.f, kk = 0.f, aa = 0.f;

    for (int c0 = 0; c0 < NPIX/NSPLIT; c0 += 256) {
        for (int i = tid; i < CAH*256; i += 768) {
            int d = i >> 8, p = i & 255;
            a_s[d][p] = ap[(size_t)d*NPIX + p0 + c0 + p];
        }
        __syncthreads();
#pragma unroll
        for (int hf = 0; hf < 2; hf++) {
            int p = hf*128 + lane*4;
            float4 qv = *(const float4*)&qp[p0 + c0 + p];
            float4 kv = *(const float4*)&kp[p0 + c0 + p];
            qq += qv.x*qv.x + qv.y*qv.y + qv.z*qv.z + qv.w*qv.w;
            kk += kv.x*kv.x + kv.y*kv.y + kv.z*kv.z + kv.w*kv.w;
            if (warp < CAH) {
                float4 av = *(const float4*)&a_s[warp][p];
                aa += av.x*av.x + av.y*av.y + av.z*av.z + av.w*av.w;
            }
#pragma unroll
            for (int d = 0; d < 12; d++) {
                float4 av = *(const float4*)&a_s[d][p];
                dq[d] += qv.x*av.x + qv.y*av.y + qv.z*av.z + qv.w*av.w;
                dk[d] += kv.x*av.x + kv.y*av.y + kv.z*av.z + kv.w*av.w;
            }
        }
        __syncthreads();
    }
#pragma unroll
    for (int off = 16; off; off >>= 1) {
#pragma unroll
        for (int d = 0; d < 12; d++) {
            dq[d] += __shfl_down_sync(0xffffffffu, dq[d], off);
            dk[d] += __shfl_down_sync(0xffffffffu, dk[d], off);
        }
        qq += __shfl_down_sync(0xffffffffu, qq, off);
        kk += __shfl_down_sync(0xffffffffu, kk, off);
        aa += __shfl_down_sync(0xffffffffu, aa, off);
    }
    if (lane == 0) {
        float* out = &g_dotp[((size_t)split*BATCH*HEADS + bh)*DOTP];
#pragma unroll
        for (int d = 0; d < 12; d++) {
            out[warp*12 + d]       = dq[d];
            out[288 + warp*12 + d] = dk[d];
        }
        out[576 + warp] = qq;
        out[600 + warp] = kk;
        if (warp < 12) out[624 + warp] = aa;
    }
}

// ================= combine: norms, softmax, M, W_eff^T slice (half) =========
#define WSLICE (C*C/64)      // 576
__global__ __launch_bounds__(256) void combine_kernel(const float* __restrict__ wo,
                                                      const float* __restrict__ ta,
                                                      const float* __restrict__ tv)
{
    __shared__ float buf[HEADS*DOTP];
    __shared__ float SA[HEADS][CQH][CAH];
    __shared__ float SK[HEADS][CAH][CQH];
    int slice = blockIdx.x, b = blockIdx.y, tid = threadIdx.x;

    for (int i = tid; i < HEADS*DOTP; i += 256) {
        int h = i / DOTP, e = i - h*DOTP;
        float s = 0.f;
#pragma unroll
        for (int sp = 0; sp < NSPLIT; sp++)
            s += g_dotp[((size_t)sp*BATCH*HEADS + b*HEADS + h)*DOTP + e];
        buf[i] = s;
    }
    __syncthreads();

    if (tid < HEADS*CQH) {
        int h = tid / CQH, c = tid % CQH;
        const float* B = &buf[h*DOTP];
        float invq = 1.f / fmaxf(sqrtf(B[576 + c]), 1e-12f);
        float tah = ta[h];
        float l[CAH], m = -1e30f;
#pragma unroll
        for (int d = 0; d < CAH; d++) {
            float inva = 1.f / fmaxf(sqrtf(B[624 + d]), 1e-12f);
            l[d] = B[c*12 + d] * invq * inva * tah;
            m = fmaxf(m, l[d]);
        }
        float s = 0.f;
#pragma unroll
        for (int d = 0; d < CAH; d++) { l[d] = expf(l[d] - m); s += l[d]; }
        float inv = 1.f / s;
#pragma unroll
        for (int d = 0; d < CAH; d++) SA[h][c][d] = l[d] * inv;
    }
    if (tid < HEADS*CAH) {
        int h = tid / CAH, d = tid % CAH;
        const float* B = &buf[h*DOTP];
        float inva = 1.f / fmaxf(sqrtf(B[624 + d]), 1e-12f);
        float tvh = tv[h];
        float l[CQH], m = -1e30f;
#pragma unroll
        for (int c = 0; c < CQH; c++) {
            float invk = 1.f / fmaxf(sqrtf(B[600 + c]), 1e-12f);
            l[c] = B[288 + c*12 + d] * invk * inva * tvh;
            m = fmaxf(m, l[c]);
        }
        float s = 0.f;
#pragma unroll
        for (int c = 0; c < CQH; c++) { l[c] = expf(l[c] - m); s += l[c]; }
        float inv = 1.f / s;
#pragma unroll
        for (int c = 0; c < CQH; c++) SK[h][d][c] = l[c] * inv;
    }
    __syncthreads();

    float* M = buf;
    for (int i = tid; i < HEADS*CQH*CQH; i += 256) {
        int h = i / (CQH*CQH), r = (i / CQH) % CQH, j = i % CQH;
        float s = 0.f;
#pragma unroll
        for (int d = 0; d < CAH; d++) s = fmaf(SA[h][r][d], SK[h][d][j], s);
        M[(h*CQH + r)*CQH + j] = s;
    }
    __syncthreads();

    int base = slice * WSLICE;
    for (int i = base + tid; i < base + WSLICE; i += 256) {
        int cv = i / C, o = i % C;
        int hv = cv / CQH, j = cv % CQH;
        float s = 0.f;
#pragma unroll
        for (int k = 0; k < CQH; k++)
            s = fmaf(wo[o*C + hv*CQH + k], M[(hv*CQH + k)*CQH + j], s);
        g_weffTh[(size_t)b*C*C + i] = __float2half_rn(s);
    }
}

// ================= launch ===================================================
extern "C" void kernel_launch(void* const* d_in, const int* in_sizes, int n_in,
                              void* d_out, int out_size)
{
    const float* x    = (const float*)d_in[0];
    const float* illu = (const float*)d_in[1];
    const float* wq   = (const float*)d_in[2];
    const float* wk   = (const float*)d_in[3];
    const float* wadw = (const float*)d_in[4];
    const float* wapw = (const float*)d_in[5];
    const float* bapw = (const float*)d_in[6];
    const float* wv   = (const float*)d_in[7];
    const float* wo   = (const float*)d_in[8];
    const float* ta   = (const float*)d_in[9];
    const float* tv   = (const float*)d_in[10];
    float* out = (float*)d_out;

    const int fat_smem = (2*ABUF + 2*BBUF)*2 + KKDIM*4;   // 49920
    const int tg_smem  = (2*ABUF + 2*BBUF)*2;             // 43008
    cudaFuncSetAttribute(fat_kernel, cudaFuncAttributeMaxDynamicSharedMemorySize, fat_smem);
    cudaFuncSetAttribute(tgemm1_kernel, cudaFuncAttributeMaxDynamicSharedMemorySize, tg_smem);

    zp_prep_kernel<<<ZP_N + PREP_N, 256>>>(wk, wv);
    sdq_kernel    <<<SDQ_N/2, 256>>>(0,        x, wq, wadw);
    sdq_kernel    <<<SDQ_N/2, 256>>>(SDQ_N/2,  x, wq, wadw);
    fat_kernel    <<<KCONV_N + TG0_N + APW_N, 256, fat_smem>>>(x, illu, wapw, bapw);
    attn_kernel   <<<dim3(NSPLIT, BATCH*HEADS), 768>>>();
    combine_kernel<<<dim3(64, BATCH), 256>>>(wo, ta, tv);
    tgemm1_kernel <<<TG0_N, 256, tg_smem>>>(out);
}